// round 15
// baseline (speedup 1.0000x reference)
#include <cuda_runtime.h>
#include <math.h>
#include <stdint.h>

#define BB 4
#define NN 4096
#define DD 1024
#define FF 64
#define MROWS (BB*NN)      // 16384
#define HID (4*DD)         // 4096
#define LCH 128            // attention chunk length
#define NCH (NN/LCH)       // 32 chunks per batch

// ---------------- scratch (static __device__ — no allocation allowed) -------
__device__ float g_xn[(size_t)MROWS*DD];
__device__ float g_q [(size_t)MROWS*FF];
__device__ float g_k [(size_t)MROWS*FF];
__device__ float g_v [(size_t)MROWS*DD];
__device__ float g_attn[(size_t)MROWS*DD];
__device__ float g_y1[(size_t)MROWS*DD];
__device__ float g_h [(size_t)MROWS*DD];
__device__ float g_hf[(size_t)MROWS*HID];
__device__ float g_S [(size_t)BB*NCH*FF*DD];   // per-chunk KV sums -> exclusive prefix
__device__ float g_ks[(size_t)BB*NCH*FF];      // per-chunk K sums -> exclusive prefix

// ---------------- LayerNorm: one CTA per row of 1024 ------------------------
__global__ void ln_kernel(const float* __restrict__ x, const float* __restrict__ w,
                          const float* __restrict__ b, float* __restrict__ y) {
    int row = blockIdx.x;
    int t = threadIdx.x;                      // 256 threads, 1 float4 each
    const float4* xr = (const float4*)(x + (size_t)row * DD);
    float4 p = xr[t];
    float s  = p.x + p.y + p.z + p.w;
    float ss = p.x*p.x + p.y*p.y + p.z*p.z + p.w*p.w;
    #pragma unroll
    for (int o = 16; o; o >>= 1) {
        s  += __shfl_down_sync(0xffffffffu, s,  o);
        ss += __shfl_down_sync(0xffffffffu, ss, o);
    }
    __shared__ float rs[8], rss[8];
    int wid = t >> 5, lid = t & 31;
    if (lid == 0) { rs[wid] = s; rss[wid] = ss; }
    __syncthreads();
    float tot = 0.f, tot2 = 0.f;
    #pragma unroll
    for (int i = 0; i < 8; i++) { tot += rs[i]; tot2 += rss[i]; }
    float mu  = tot * (1.0f / DD);
    float var = tot2 * (1.0f / DD) - mu * mu;
    float inv = rsqrtf(var + 1e-5f);
    float4 wv = ((const float4*)w)[t];
    float4 bv = ((const float4*)b)[t];
    float4 o;
    o.x = (p.x - mu) * inv * wv.x + bv.x;
    o.y = (p.y - mu) * inv * wv.y + bv.y;
    o.z = (p.z - mu) * inv * wv.z + bv.z;
    o.w = (p.w - mu) * inv * wv.w + bv.w;
    ((float4*)(y + (size_t)row * DD))[t] = o;
}

// ---------------- fp32 SIMT GEMM (kept for small Q/K projections) -----------
// EPI: 0 = none, 1 = elu(x)+1, 2 = gelu exact, 3 = residual add
template<int EPI>
__global__ void gemm_tn(const float* __restrict__ A, const float* __restrict__ W,
                        const float* __restrict__ bias, const float* __restrict__ R,
                        float* __restrict__ C, int M, int Nout, int Kd) {
    __shared__ float As[16][68];
    __shared__ float Ws[16][68];
    int t  = threadIdx.x;
    int tx = t & 15, ty = t >> 4;
    int m0 = blockIdx.y * 64, n0 = blockIdx.x * 64;
    int lr = t >> 2;
    int lc = (t & 3) * 4;
    const float* Ag = A + (size_t)(m0 + lr) * Kd + lc;
    const float* Wg = W + (size_t)(n0 + lr) * Kd + lc;

    float acc[4][4];
    #pragma unroll
    for (int i = 0; i < 4; i++)
        #pragma unroll
        for (int j = 0; j < 4; j++) acc[i][j] = 0.f;

    for (int k0 = 0; k0 < Kd; k0 += 16) {
        float4 av = *(const float4*)(Ag + k0);
        float4 wv = *(const float4*)(Wg + k0);
        As[lc+0][lr] = av.x; As[lc+1][lr] = av.y;
        As[lc+2][lr] = av.z; As[lc+3][lr] = av.w;
        Ws[lc+0][lr] = wv.x; Ws[lc+1][lr] = wv.y;
        Ws[lc+2][lr] = wv.z; Ws[lc+3][lr] = wv.w;
        __syncthreads();
        #pragma unroll
        for (int kk = 0; kk < 16; kk++) {
            float4 a = *(const float4*)&As[kk][ty * 4];
            float4 b = *(const float4*)&Ws[kk][tx * 4];
            acc[0][0] += a.x*b.x; acc[0][1] += a.x*b.y; acc[0][2] += a.x*b.z; acc[0][3] += a.x*b.w;
            acc[1][0] += a.y*b.x; acc[1][1] += a.y*b.y; acc[1][2] += a.y*b.z; acc[1][3] += a.y*b.w;
            acc[2][0] += a.z*b.x; acc[2][1] += a.z*b.y; acc[2][2] += a.z*b.z; acc[2][3] += a.z*b.w;
            acc[3][0] += a.w*b.x; acc[3][1] += a.w*b.y; acc[3][2] += a.w*b.z; acc[3][3] += a.w*b.w;
        }
        __syncthreads();
    }

    #pragma unroll
    for (int i = 0; i < 4; i++) {
        int m = m0 + ty * 4 + i;
        #pragma unroll
        for (int j = 0; j < 4; j++) {
            int n = n0 + tx * 4 + j;
            float v = acc[i][j] + bias[n];
            if (EPI == 1) v = (v > 0.f) ? (v + 1.f) : expf(v);
            else if (EPI == 2) v = 0.5f * v * (1.f + erff(v * 0.70710678118f));
            else if (EPI == 3) v += R[(size_t)m * Nout + n];
            C[(size_t)m * Nout + n] = v;
        }
    }
}

// ---------------- tf32 tensor-core GEMM: C = A @ W^T + bias (+epilogue) -----
__device__ __forceinline__ uint32_t f2tf32(float x) {
    uint32_t r; asm("cvt.rna.tf32.f32 %0, %1;" : "=r"(r) : "f"(x)); return r;
}

__device__ __forceinline__ void mma_tf32(float* c, const uint32_t* a, const uint32_t* b) {
    asm volatile(
        "mma.sync.aligned.m16n8k8.row.col.f32.tf32.tf32.f32 "
        "{%0,%1,%2,%3}, {%4,%5,%6,%7}, {%8,%9}, {%0,%1,%2,%3};\n"
        : "+f"(c[0]), "+f"(c[1]), "+f"(c[2]), "+f"(c[3])
        : "r"(a[0]), "r"(a[1]), "r"(a[2]), "r"(a[3]), "r"(b[0]), "r"(b[1]));
}

// Block tile 128x128, BK=16. 8 warps, each 64x32 (4x4 m16n8k8 tiles per k-step).
template<int EPI>
__global__ void __launch_bounds__(256, 2)
gemm_tc(const float* __restrict__ A, const float* __restrict__ W,
        const float* __restrict__ bias, const float* __restrict__ R,
        float* __restrict__ C, int M, int Nout, int Kd) {
    __shared__ uint32_t As[16][136];   // [k][m], pad 8 -> conflict-free frags
    __shared__ uint32_t Ws[16][136];   // [k][n]
    int tid = threadIdx.x;
    int wid = tid >> 5, lane = tid & 31;
    int warp_m = (wid >> 2) * 64;      // 0,64
    int warp_n = (wid & 3) * 32;       // 0,32,64,96
    int m0 = blockIdx.y * 128, n0 = blockIdx.x * 128;
    int row = lane >> 2, colq = lane & 3;

    int lr = tid >> 2;                 // 0..63
    int lk = (tid & 3) * 4;            // 0,4,8,12
    const float* Ag0 = A + (size_t)(m0 + lr) * Kd + lk;
    const float* Ag1 = A + (size_t)(m0 + lr + 64) * Kd + lk;
    const float* Wg0 = W + (size_t)(n0 + lr) * Kd + lk;
    const float* Wg1 = W + (size_t)(n0 + lr + 64) * Kd + lk;

    float acc[4][4][4];
    #pragma unroll
    for (int mi = 0; mi < 4; mi++)
        #pragma unroll
        for (int ni = 0; ni < 4; ni++)
            #pragma unroll
            for (int r = 0; r < 4; r++) acc[mi][ni][r] = 0.f;

    for (int k0 = 0; k0 < Kd; k0 += 16) {
        float4 a0 = *(const float4*)(Ag0 + k0);
        float4 a1 = *(const float4*)(Ag1 + k0);
        float4 w0 = *(const float4*)(Wg0 + k0);
        float4 w1 = *(const float4*)(Wg1 + k0);
        As[lk+0][lr]    = f2tf32(a0.x); As[lk+1][lr]    = f2tf32(a0.y);
        As[lk+2][lr]    = f2tf32(a0.z); As[lk+3][lr]    = f2tf32(a0.w);
        As[lk+0][lr+64] = f2tf32(a1.x); As[lk+1][lr+64] = f2tf32(a1.y);
        As[lk+2][lr+64] = f2tf32(a1.z); As[lk+3][lr+64] = f2tf32(a1.w);
        Ws[lk+0][lr]    = f2tf32(w0.x); Ws[lk+1][lr]    = f2tf32(w0.y);
        Ws[lk+2][lr]    = f2tf32(w0.z); Ws[lk+3][lr]    = f2tf32(w0.w);
        Ws[lk+0][lr+64] = f2tf32(w1.x); Ws[lk+1][lr+64] = f2tf32(w1.y);
        Ws[lk+2][lr+64] = f2tf32(w1.z); Ws[lk+3][lr+64] = f2tf32(w1.w);
        __syncthreads();

        #pragma unroll
        for (int ks = 0; ks < 2; ks++) {
            const int kb = ks * 8;
            uint32_t af[4][4], bf[4][2];
            #pragma unroll
            for (int mi = 0; mi < 4; mi++) {
                int m = warp_m + mi * 16 + row;
                af[mi][0] = As[kb + colq    ][m];
                af[mi][1] = As[kb + colq    ][m + 8];
                af[mi][2] = As[kb + colq + 4][m];
                af[mi][3] = As[kb + colq + 4][m + 8];
            }
            #pragma unroll
            for (int ni = 0; ni < 4; ni++) {
                int n = warp_n + ni * 8 + row;
                bf[ni][0] = Ws[kb + colq    ][n];
                bf[ni][1] = Ws[kb + colq + 4][n];
            }
            #pragma unroll
            for (int mi = 0; mi < 4; mi++)
                #pragma unroll
                for (int ni = 0; ni < 4; ni++)
                    mma_tf32(acc[mi][ni], af[mi], bf[ni]);
        }
        __syncthreads();
    }

    // epilogue: c0:(r,c) c1:(r,c+1) c2:(r+8,c) c3:(r+8,c+1)
    #pragma unroll
    for (int mi = 0; mi < 4; mi++) {
        #pragma unroll
        for (int ni = 0; ni < 4; ni++) {
            int rbase = m0 + warp_m + mi * 16 + row;
            int cbase = n0 + warp_n + ni * 8 + colq * 2;
            #pragma unroll
            for (int r = 0; r < 4; r++) {
                int m = rbase + ((r >> 1) ? 8 : 0);
                int n = cbase + (r & 1);
                float v = acc[mi][ni][r] + bias[n];
                if (EPI == 2) v = 0.5f * v * (1.f + erff(v * 0.70710678118f));
                else if (EPI == 3) v += R[(size_t)m * Nout + n];
                C[(size_t)m * Nout + n] = v;
            }
        }
    }
}

// ---------------- chunked causal linear attention ----------------------------
// Pass 1: per-chunk sums  S_c[f][d] = sum_{i in chunk} k_i[f] v_i[d],  ks_c[f].
// grid (NCH, DD/128, BB), 256 threads: f = tid&63, dgroup = tid>>6 (32 d each)
__global__ void chunk_sums(const float* __restrict__ K, const float* __restrict__ V,
                           float* __restrict__ S, float* __restrict__ ksum) {
    int c = blockIdx.x, b = blockIdx.z;
    int d0blk = blockIdx.y * 128;
    int tid = threadIdx.x;
    int f = tid & 63, dg = tid >> 6;
    __shared__ float Ksh[32][68];
    __shared__ float Vsh[32][132];
    float acc[32];
    #pragma unroll
    for (int j = 0; j < 32; j++) acc[j] = 0.f;
    float ksacc = 0.f;

    const float* Kb = K + ((size_t)b * NN + (size_t)c * LCH) * FF;
    const float* Vb = V + ((size_t)b * NN + (size_t)c * LCH) * DD + d0blk;

    for (int kt = 0; kt < 4; kt++) {
        {   // load K rows [kt*32, kt*32+32) : 32x64
            int r = tid >> 3, fc = (tid & 7) * 8;
            const float* src = Kb + (size_t)(kt * 32 + r) * FF + fc;
            float4 v0 = *(const float4*)src;
            float4 v1 = *(const float4*)(src + 4);
            *(float4*)&Ksh[r][fc]     = v0;
            *(float4*)&Ksh[r][fc + 4] = v1;
        }
        {   // load V rows: 32x128
            int r = tid >> 3, dc = (tid & 7) * 16;
            const float* src = Vb + (size_t)(kt * 32 + r) * DD + dc;
            #pragma unroll
            for (int j = 0; j < 4; j++)
                *(float4*)&Vsh[r][dc + j * 4] = *(const float4*)(src + j * 4);
        }
        __syncthreads();
        #pragma unroll 4
        for (int r = 0; r < 32; r++) {
            float kf = Ksh[r][f];
            if (dg == 0) ksacc += kf;
            const float4* vr = (const float4*)&Vsh[r][dg * 32];
            #pragma unroll
            for (int j4 = 0; j4 < 8; j4++) {
                float4 vv = vr[j4];
                acc[j4*4+0] = fmaf(kf, vv.x, acc[j4*4+0]);
                acc[j4*4+1] = fmaf(kf, vv.y, acc[j4*4+1]);
                acc[j4*4+2] = fmaf(kf, vv.z, acc[j4*4+2]);
                acc[j4*4+3] = fmaf(kf, vv.w, acc[j4*4+3]);
            }
        }
        __syncthreads();
    }

    float* Sp = S + (((size_t)b * NCH + c) * FF + f) * DD + d0blk + dg * 32;
    #pragma unroll
    for (int j4 = 0; j4 < 8; j4++)
        *(float4*)(Sp + j4 * 4) = make_float4(acc[j4*4+0], acc[j4*4+1], acc[j4*4+2], acc[j4*4+3]);
    if (dg == 0) ksum[((size_t)b * NCH + c) * FF + f] = ksacc;
}

// Pass 2a: in-place exclusive prefix of S over chunks. One thread per (b,f,d).
__global__ void prefix_S(float* __restrict__ S) {
    size_t g = (size_t)blockIdx.x * 256 + threadIdx.x;  // 0 .. BB*FF*DD-1
    int d = (int)(g % DD);
    int f = (int)((g / DD) % FF);
    int b = (int)(g / ((size_t)DD * FF));
    float run = 0.f;
    for (int c = 0; c < NCH; c++) {
        size_t idx = (((size_t)b * NCH + c) * FF + f) * DD + d;
        float t = S[idx];
        S[idx] = run;
        run += t;
    }
}

// Pass 2b: exclusive prefix of ksum. grid BB, 64 threads.
__global__ void prefix_ks(float* __restrict__ ks) {
    int b = blockIdx.x, f = threadIdx.x;
    float run = 0.f;
    for (int c = 0; c < NCH; c++) {
        size_t idx = ((size_t)b * NCH + c) * FF + f;
        float t = ks[idx];
        ks[idx] = run;
        run += t;
    }
}

// Pass 3: within-chunk scan. grid (NCH, DD/128, BB), 128 threads (one d each).
__global__ void attn_scan_chunk(const float* __restrict__ Q, const float* __restrict__ K,
                                const float* __restrict__ V, const float* __restrict__ S,
                                const float* __restrict__ ksp, float* __restrict__ O) {
    int c = blockIdx.x, b = blockIdx.z;
    int t = threadIdx.x;
    int d = blockIdx.y * 128 + t;
    __shared__ float qs[64], ks[64], Kss[64];
    if (t < 64) Kss[t] = ksp[((size_t)b * NCH + c) * FF + t];

    float kv[64];
    const float* Sp = S + (((size_t)b * NCH + c) * FF) * DD + d;
    #pragma unroll
    for (int f = 0; f < 64; f++) kv[f] = Sp[(size_t)f * DD];

    size_t r0 = (size_t)b * NN + (size_t)c * LCH;
    const float* Qb = Q + r0 * FF;
    const float* Kb = K + r0 * FF;
    const float* Vb = V + r0 * DD + d;
    float*       Ob = O + r0 * DD + d;

    for (int i = 0; i < LCH; i++) {
        if (t < 64) qs[t] = Qb[(size_t)i * FF + t];
        else        ks[t - 64] = Kb[(size_t)i * FF + (t - 64)];
        __syncthreads();                              // qs/ks/Kss valid
        float vd = Vb[(size_t)i * DD];
        float num = 0.f, den = 0.f;
        #pragma unroll
        for (int f = 0; f < 64; f++) {
            float kf = ks[f];
            kv[f] = fmaf(kf, vd, kv[f]);
            num   = fmaf(qs[f], kv[f], num);
            den   = fmaf(qs[f], Kss[f] + kf, den);
        }
        Ob[(size_t)i * DD] = num / (den + 1e-6f);
        __syncthreads();                              // reads done
        if (t >= 64) Kss[t - 64] += ks[t - 64];
    }
}

// ---------------- launch ------------------------------------------------------
extern "C" void kernel_launch(void* const* d_in, const int* in_sizes, int n_in,
                              void* d_out, int out_size) {
    const float* x    = (const float*)d_in[0];
    const float* ln1w = (const float*)d_in[1];
    const float* ln1b = (const float*)d_in[2];
    const float* qw   = (const float*)d_in[3];
    const float* qb   = (const float*)d_in[4];
    const float* kw   = (const float*)d_in[5];
    const float* kb   = (const float*)d_in[6];
    const float* vw   = (const float*)d_in[7];
    const float* vb   = (const float*)d_in[8];
    const float* ow   = (const float*)d_in[9];
    const float* ob   = (const float*)d_in[10];
    const float* ln2w = (const float*)d_in[11];
    const float* ln2b = (const float*)d_in[12];
    const float* f1w  = (const float*)d_in[13];
    const float* f1b  = (const float*)d_in[14];
    const float* f2w  = (const float*)d_in[15];
    const float* f2b  = (const float*)d_in[16];
    float* out = (float*)d_out;

    float *xn, *q, *k, *v, *attn, *y1, *h, *hf, *S, *ks;
    cudaGetSymbolAddress((void**)&xn,   g_xn);
    cudaGetSymbolAddress((void**)&q,    g_q);
    cudaGetSymbolAddress((void**)&k,    g_k);
    cudaGetSymbolAddress((void**)&v,    g_v);
    cudaGetSymbolAddress((void**)&attn, g_attn);
    cudaGetSymbolAddress((void**)&y1,   g_y1);
    cudaGetSymbolAddress((void**)&h,    g_h);
    cudaGetSymbolAddress((void**)&hf,   g_hf);
    cudaGetSymbolAddress((void**)&S,    g_S);
    cudaGetSymbolAddress((void**)&ks,   g_ks);

    // 1. x_norm = LN1(x)
    ln_kernel<<<MROWS, 256>>>(x, ln1w, ln1b, xn);
    // 2. Q = elu(xn @ qw^T + qb)+1 ; K likewise (small N=64 -> SIMT)
    gemm_tn<1><<<dim3(1, MROWS/64), 256>>>(xn, qw, qb, nullptr, q, MROWS, FF, DD);
    gemm_tn<1><<<dim3(1, MROWS/64), 256>>>(xn, kw, kb, nullptr, k, MROWS, FF, DD);
    // 3. V = xn @ vw^T + vb  (tf32 tensor cores)
    gemm_tc<0><<<dim3(DD/128, MROWS/128), 256>>>(xn, vw, vb, nullptr, v, MROWS, DD, DD);
    // 4. chunked causal linear attention
    chunk_sums<<<dim3(NCH, DD/128, BB), 256>>>(k, v, S, ks);
    prefix_S<<<(BB*FF*DD)/256, 256>>>(S);
    prefix_ks<<<BB, 64>>>(ks);
    attn_scan_chunk<<<dim3(NCH, DD/128, BB), 128>>>(q, k, v, S, ks, attn);
    // 5. y1 = x + attn @ ow^T + ob
    gemm_tc<3><<<dim3(DD/128, MROWS/128), 256>>>(attn, ow, ob, x, y1, MROWS, DD, DD);
    // 6. h = LN2(y1)
    ln_kernel<<<MROWS, 256>>>(y1, ln2w, ln2b, h);
    // 7. hf = gelu(h @ f1w^T + f1b)
    gemm_tc<2><<<dim3(HID/128, MROWS/128), 256>>>(h, f1w, f1b, nullptr, hf, MROWS, HID, DD);
    // 8. out = y1 + hf @ f2w^T + f2b
    gemm_tc<3><<<dim3(DD/128, MROWS/128), 256>>>(hf, f2w, f2b, y1, out, MROWS, DD, HID);
}

// round 16
// speedup vs baseline: 1.3100x; 1.3100x over previous
#include <cuda_runtime.h>
#include <math.h>
#include <stdint.h>

#define BB 4
#define NN 4096
#define DD 1024
#define FF 64
#define MROWS (BB*NN)      // 16384
#define HID (4*DD)         // 4096
#define LCH 128            // attention chunk length
#define NCH (NN/LCH)       // 32 chunks per batch
#define STG 3              // cp.async pipeline stages
#define SROW 20            // smem row stride (16 + pad 4 floats)

// ---------------- scratch (static __device__ — no allocation allowed) -------
__device__ float g_xn[(size_t)MROWS*DD];
__device__ float g_q [(size_t)MROWS*FF];
__device__ float g_k [(size_t)MROWS*FF];
__device__ float g_v [(size_t)MROWS*DD];
__device__ float g_attn[(size_t)MROWS*DD];
__device__ float g_y1[(size_t)MROWS*DD];
__device__ float g_h [(size_t)MROWS*DD];
__device__ float g_hf[(size_t)MROWS*HID];
__device__ float g_S [(size_t)BB*NCH*FF*DD];
__device__ float g_ks[(size_t)BB*NCH*FF];
// tf32-rounded weights
__device__ float g_wv [(size_t)DD*DD];
__device__ float g_wo [(size_t)DD*DD];
__device__ float g_w1 [(size_t)HID*DD];
__device__ float g_w2 [(size_t)DD*HID];
__device__ float g_wqk[(size_t)128*DD];   // rows 0..63 = qw, 64..127 = kw

// ---------------- helpers ----------------------------------------------------
__device__ __forceinline__ uint32_t f2tf32(float x) {
    uint32_t r; asm("cvt.rna.tf32.f32 %0, %1;" : "=r"(r) : "f"(x)); return r;
}
__device__ __forceinline__ void cp16(float* s, const float* g) {
    uint32_t sa = (uint32_t)__cvta_generic_to_shared(s);
    asm volatile("cp.async.cg.shared.global [%0], [%1], 16;" :: "r"(sa), "l"(g));
}
__device__ __forceinline__ void mma_tf32(float* c, const uint32_t* a, const uint32_t* b) {
    asm volatile(
        "mma.sync.aligned.m16n8k8.row.col.f32.tf32.tf32.f32 "
        "{%0,%1,%2,%3}, {%4,%5,%6,%7}, {%8,%9}, {%0,%1,%2,%3};\n"
        : "+f"(c[0]), "+f"(c[1]), "+f"(c[2]), "+f"(c[3])
        : "r"(a[0]), "r"(a[1]), "r"(a[2]), "r"(a[3]), "r"(b[0]), "r"(b[1]));
}

// ---------------- tf32 rounding pre-pass (weights) ---------------------------
__global__ void round_tf32(const float* __restrict__ in, float* __restrict__ out, int n4) {
    int i = blockIdx.x * 256 + threadIdx.x;
    if (i >= n4) return;
    float4 v = ((const float4*)in)[i];
    float4 o;
    o.x = __uint_as_float(f2tf32(v.x));
    o.y = __uint_as_float(f2tf32(v.y));
    o.z = __uint_as_float(f2tf32(v.z));
    o.w = __uint_as_float(f2tf32(v.w));
    ((float4*)out)[i] = o;
}

// ---------------- LayerNorm: one CTA per row of 1024 ------------------------
__global__ void ln_kernel(const float* __restrict__ x, const float* __restrict__ w,
                          const float* __restrict__ b, float* __restrict__ y) {
    int row = blockIdx.x;
    int t = threadIdx.x;
    const float4* xr = (const float4*)(x + (size_t)row * DD);
    float4 p = xr[t];
    float s  = p.x + p.y + p.z + p.w;
    float ss = p.x*p.x + p.y*p.y + p.z*p.z + p.w*p.w;
    #pragma unroll
    for (int o = 16; o; o >>= 1) {
        s  += __shfl_down_sync(0xffffffffu, s,  o);
        ss += __shfl_down_sync(0xffffffffu, ss, o);
    }
    __shared__ float rs[8], rss[8];
    int wid = t >> 5, lid = t & 31;
    if (lid == 0) { rs[wid] = s; rss[wid] = ss; }
    __syncthreads();
    float tot = 0.f, tot2 = 0.f;
    #pragma unroll
    for (int i = 0; i < 8; i++) { tot += rs[i]; tot2 += rss[i]; }
    float mu  = tot * (1.0f / DD);
    float var = tot2 * (1.0f / DD) - mu * mu;
    float inv = rsqrtf(var + 1e-5f);
    float4 wv = ((const float4*)w)[t];
    float4 bv = ((const float4*)b)[t];
    float4 o;
    o.x = (p.x - mu) * inv * wv.x + bv.x;
    o.y = (p.y - mu) * inv * wv.y + bv.y;
    o.z = (p.z - mu) * inv * wv.z + bv.z;
    o.w = (p.w - mu) * inv * wv.w + bv.w;
    ((float4*)(y + (size_t)row * DD))[t] = o;
}

// ---------------- tf32 tensor-core GEMM, cp.async 3-stage pipeline ----------
// C[M,Nout] = A[M,Kd] @ W[Nout,Kd]^T + bias (+ epilogue)
// W must be pre-rounded to tf32. A is cvt.rna'd at fragment load.
// EPI: 0 none, 1 elu+1 (DUAL: split outputs q/k), 2 gelu, 3 residual
// Block 128x128, BK=16, 8 warps of 64x32.
template<int EPI, bool DUAL>
__global__ void __launch_bounds__(256, 2)
gemm_tc(const float* __restrict__ A, const float* __restrict__ W,
        const float* __restrict__ bias, const float* __restrict__ bias2,
        const float* __restrict__ R, float* __restrict__ C, float* __restrict__ C2,
        int M, int Nout, int Kd) {
    extern __shared__ float sm[];
    float* Asm = sm;                     // [STG][128][SROW]
    float* Wsm = sm + STG * 128 * SROW;  // [STG][128][SROW]

    int tid = threadIdx.x;
    int wid = tid >> 5, lane = tid & 31;
    int warp_m = (wid >> 2) * 64;
    int warp_n = (wid & 3) * 32;
    int m0 = blockIdx.y * 128, n0 = blockIdx.x * 128;
    int row = lane >> 2, colq = lane & 3;

    // cp.async mapping: 512 16B chunks per operand per stage; 2 per thread
    int ar0 = tid >> 1;                    // chunk tid    : rows 0..127 (c>>2 over 0..255)
    int ak0 = (tid & 1) * 8;               // hmm — recompute properly below
    // proper: chunk c in 0..511, row=c>>2, kcol=(c&3)*4
    int c0 = tid, c1 = tid + 256;
    int r0c = c0 >> 2, k0c = (c0 & 3) * 4;
    int r1c = c1 >> 2, k1c = (c1 & 3) * 4;
    (void)ar0; (void)ak0;

    const float* Ap0 = A + (size_t)(m0 + r0c) * Kd + k0c;
    const float* Ap1 = A + (size_t)(m0 + r1c) * Kd + k1c;
    const float* Wp0 = W + (size_t)(n0 + r0c) * Kd + k0c;
    const float* Wp1 = W + (size_t)(n0 + r1c) * Kd + k1c;
    float* As0 = Asm + r0c * SROW + k0c;
    float* As1 = Asm + r1c * SROW + k1c;
    float* Ws0 = Wsm + r0c * SROW + k0c;
    float* Ws1 = Wsm + r1c * SROW + k1c;

    float acc[4][4][4];
    #pragma unroll
    for (int mi = 0; mi < 4; mi++)
        #pragma unroll
        for (int ni = 0; ni < 4; ni++)
            #pragma unroll
            for (int r = 0; r < 4; r++) acc[mi][ni][r] = 0.f;

    int ntiles = Kd >> 4;
    const int SSTRIDE = 128 * SROW;

    // prologue: prefetch tiles 0..STG-2
    #pragma unroll
    for (int p = 0; p < STG - 1; p++) {
        size_t ko = (size_t)p * 16;
        cp16(As0 + p * SSTRIDE, Ap0 + ko);
        cp16(As1 + p * SSTRIDE, Ap1 + ko);
        cp16(Ws0 + p * SSTRIDE, Wp0 + ko);
        cp16(Ws1 + p * SSTRIDE, Wp1 + ko);
        asm volatile("cp.async.commit_group;");
    }

    for (int i = 0; i < ntiles; i++) {
        if (i + 1 < ntiles) { asm volatile("cp.async.wait_group 1;"); }
        else                { asm volatile("cp.async.wait_group 0;"); }
        __syncthreads();

        if (i + STG - 1 < ntiles) {
            int s = (i + STG - 1) % STG;
            size_t ko = (size_t)(i + STG - 1) * 16;
            cp16(As0 + s * SSTRIDE, Ap0 + ko);
            cp16(As1 + s * SSTRIDE, Ap1 + ko);
            cp16(Ws0 + s * SSTRIDE, Wp0 + ko);
            cp16(Ws1 + s * SSTRIDE, Wp1 + ko);
        }
        asm volatile("cp.async.commit_group;");

        const float* Ab = Asm + (i % STG) * SSTRIDE;
        const float* Wb = Wsm + (i % STG) * SSTRIDE;
        #pragma unroll
        for (int ks = 0; ks < 2; ks++) {
            const int kb = ks * 8;
            uint32_t af[4][4], bf[4][2];
            #pragma unroll
            for (int mi = 0; mi < 4; mi++) {
                int m = warp_m + mi * 16 + row;
                af[mi][0] = f2tf32(Ab[(m    ) * SROW + kb + colq    ]);
                af[mi][1] = f2tf32(Ab[(m + 8) * SROW + kb + colq    ]);
                af[mi][2] = f2tf32(Ab[(m    ) * SROW + kb + colq + 4]);
                af[mi][3] = f2tf32(Ab[(m + 8) * SROW + kb + colq + 4]);
            }
            #pragma unroll
            for (int ni = 0; ni < 4; ni++) {
                int n = warp_n + ni * 8 + row;
                bf[ni][0] = __float_as_uint(Wb[n * SROW + kb + colq    ]);
                bf[ni][1] = __float_as_uint(Wb[n * SROW + kb + colq + 4]);
            }
            #pragma unroll
            for (int mi = 0; mi < 4; mi++)
                #pragma unroll
                for (int ni = 0; ni < 4; ni++)
                    mma_tf32(acc[mi][ni], af[mi], bf[ni]);
        }
        __syncthreads();
    }

    // epilogue: c0:(r,c) c1:(r,c+1) c2:(r+8,c) c3:(r+8,c+1)
    #pragma unroll
    for (int mi = 0; mi < 4; mi++) {
        #pragma unroll
        for (int ni = 0; ni < 4; ni++) {
            int rbase = m0 + warp_m + mi * 16 + row;
            int cbase = n0 + warp_n + ni * 8 + colq * 2;
            #pragma unroll
            for (int r = 0; r < 4; r++) {
                int m = rbase + ((r >> 1) ? 8 : 0);
                int n = cbase + (r & 1);
                if (DUAL) {
                    float v = acc[mi][ni][r] + (n < 64 ? bias[n] : bias2[n - 64]);
                    v = (v > 0.f) ? (v + 1.f) : expf(v);     // elu + 1
                    if (n < 64) C [(size_t)m * FF + n]      = v;
                    else        C2[(size_t)m * FF + n - 64] = v;
                } else {
                    float v = acc[mi][ni][r] + bias[n];
                    if (EPI == 2) v = 0.5f * v * (1.f + erff(v * 0.70710678118f));
                    else if (EPI == 3) v += R[(size_t)m * Nout + n];
                    C[(size_t)m * Nout + n] = v;
                }
            }
        }
    }
}

// ---------------- chunked causal linear attention ----------------------------
__global__ void chunk_sums(const float* __restrict__ K, const float* __restrict__ V,
                           float* __restrict__ S, float* __restrict__ ksum) {
    int c = blockIdx.x, b = blockIdx.z;
    int d0blk = blockIdx.y * 128;
    int tid = threadIdx.x;
    int f = tid & 63, dg = tid >> 6;
    __shared__ float Ksh[32][68];
    __shared__ float Vsh[32][132];
    float acc[32];
    #pragma unroll
    for (int j = 0; j < 32; j++) acc[j] = 0.f;
    float ksacc = 0.f;

    const float* Kb = K + ((size_t)b * NN + (size_t)c * LCH) * FF;
    const float* Vb = V + ((size_t)b * NN + (size_t)c * LCH) * DD + d0blk;

    for (int kt = 0; kt < 4; kt++) {
        {
            int r = tid >> 3, fc = (tid & 7) * 8;
            const float* src = Kb + (size_t)(kt * 32 + r) * FF + fc;
            float4 v0 = *(const float4*)src;
            float4 v1 = *(const float4*)(src + 4);
            *(float4*)&Ksh[r][fc]     = v0;
            *(float4*)&Ksh[r][fc + 4] = v1;
        }
        {
            int r = tid >> 3, dc = (tid & 7) * 16;
            const float* src = Vb + (size_t)(kt * 32 + r) * DD + dc;
            #pragma unroll
            for (int j = 0; j < 4; j++)
                *(float4*)&Vsh[r][dc + j * 4] = *(const float4*)(src + j * 4);
        }
        __syncthreads();
        #pragma unroll 4
        for (int r = 0; r < 32; r++) {
            float kf = Ksh[r][f];
            if (dg == 0) ksacc += kf;
            const float4* vr = (const float4*)&Vsh[r][dg * 32];
            #pragma unroll
            for (int j4 = 0; j4 < 8; j4++) {
                float4 vv = vr[j4];
                acc[j4*4+0] = fmaf(kf, vv.x, acc[j4*4+0]);
                acc[j4*4+1] = fmaf(kf, vv.y, acc[j4*4+1]);
                acc[j4*4+2] = fmaf(kf, vv.z, acc[j4*4+2]);
                acc[j4*4+3] = fmaf(kf, vv.w, acc[j4*4+3]);
            }
        }
        __syncthreads();
    }

    float* Sp = S + (((size_t)b * NCH + c) * FF + f) * DD + d0blk + dg * 32;
    #pragma unroll
    for (int j4 = 0; j4 < 8; j4++)
        *(float4*)(Sp + j4 * 4) = make_float4(acc[j4*4+0], acc[j4*4+1], acc[j4*4+2], acc[j4*4+3]);
    if (dg == 0) ksum[((size_t)b * NCH + c) * FF + f] = ksacc;
}

__global__ void prefix_S(float* __restrict__ S) {
    size_t g = (size_t)blockIdx.x * 256 + threadIdx.x;
    int d = (int)(g % DD);
    int f = (int)((g / DD) % FF);
    int b = (int)(g / ((size_t)DD * FF));
    float run = 0.f;
    for (int c = 0; c < NCH; c++) {
        size_t idx = (((size_t)b * NCH + c) * FF + f) * DD + d;
        float t = S[idx];
        S[idx] = run;
        run += t;
    }
}

__global__ void prefix_ks(float* __restrict__ ks) {
    int b = blockIdx.x, f = threadIdx.x;
    float run = 0.f;
    for (int c = 0; c < NCH; c++) {
        size_t idx = ((size_t)b * NCH + c) * FF + f;
        float t = ks[idx];
        ks[idx] = run;
        run += t;
    }
}

__global__ void attn_scan_chunk(const float* __restrict__ Q, const float* __restrict__ K,
                                const float* __restrict__ V, const float* __restrict__ S,
                                const float* __restrict__ ksp, float* __restrict__ O) {
    int c = blockIdx.x, b = blockIdx.z;
    int t = threadIdx.x;
    int d = blockIdx.y * 128 + t;
    __shared__ float qs[64], ks[64], Kss[64];
    if (t < 64) Kss[t] = ksp[((size_t)b * NCH + c) * FF + t];

    float kv[64];
    const float* Sp = S + (((size_t)b * NCH + c) * FF) * DD + d;
    #pragma unroll
    for (int f = 0; f < 64; f++) kv[f] = Sp[(size_t)f * DD];

    size_t r0 = (size_t)b * NN + (size_t)c * LCH;
    const float* Qb = Q + r0 * FF;
    const float* Kb = K + r0 * FF;
    const float* Vb = V + r0 * DD + d;
    float*       Ob = O + r0 * DD + d;

    for (int i = 0; i < LCH; i++) {
        if (t < 64) qs[t] = Qb[(size_t)i * FF + t];
        else        ks[t - 64] = Kb[(size_t)i * FF + (t - 64)];
        __syncthreads();
        float vd = Vb[(size_t)i * DD];
        float num = 0.f, den = 0.f;
        #pragma unroll
        for (int f = 0; f < 64; f++) {
            float kf = ks[f];
            kv[f] = fmaf(kf, vd, kv[f]);
            num   = fmaf(qs[f], kv[f], num);
            den   = fmaf(qs[f], Kss[f] + kf, den);
        }
        Ob[(size_t)i * DD] = num / (den + 1e-6f);
        __syncthreads();
        if (t >= 64) Kss[t - 64] += ks[t - 64];
    }
}

// ---------------- launch ------------------------------------------------------
extern "C" void kernel_launch(void* const* d_in, const int* in_sizes, int n_in,
                              void* d_out, int out_size) {
    const float* x    = (const float*)d_in[0];
    const float* ln1w = (const float*)d_in[1];
    const float* ln1b = (const float*)d_in[2];
    const float* qw   = (const float*)d_in[3];
    const float* qb   = (const float*)d_in[4];
    const float* kw   = (const float*)d_in[5];
    const float* kb   = (const float*)d_in[6];
    const float* vw   = (const float*)d_in[7];
    const float* vb   = (const float*)d_in[8];
    const float* ow   = (const float*)d_in[9];
    const float* ob   = (const float*)d_in[10];
    const float* ln2w = (const float*)d_in[11];
    const float* ln2b = (const float*)d_in[12];
    const float* f1w  = (const float*)d_in[13];
    const float* f1b  = (const float*)d_in[14];
    const float* f2w  = (const float*)d_in[15];
    const float* f2b  = (const float*)d_in[16];
    float* out = (float*)d_out;

    float *xn, *q, *k, *v, *attn, *y1, *h, *hf, *S, *ks;
    float *wv, *wo, *w1, *w2, *wqk;
    cudaGetSymbolAddress((void**)&xn,   g_xn);
    cudaGetSymbolAddress((void**)&q,    g_q);
    cudaGetSymbolAddress((void**)&k,    g_k);
    cudaGetSymbolAddress((void**)&v,    g_v);
    cudaGetSymbolAddress((void**)&attn, g_attn);
    cudaGetSymbolAddress((void**)&y1,   g_y1);
    cudaGetSymbolAddress((void**)&h,    g_h);
    cudaGetSymbolAddress((void**)&hf,   g_hf);
    cudaGetSymbolAddress((void**)&S,    g_S);
    cudaGetSymbolAddress((void**)&ks,   g_ks);
    cudaGetSymbolAddress((void**)&wv,   g_wv);
    cudaGetSymbolAddress((void**)&wo,   g_wo);
    cudaGetSymbolAddress((void**)&w1,   g_w1);
    cudaGetSymbolAddress((void**)&w2,   g_w2);
    cudaGetSymbolAddress((void**)&wqk,  g_wqk);

    const int SMEM = STG * 128 * SROW * 2 * (int)sizeof(float);  // 61440
    cudaFuncSetAttribute(gemm_tc<0,false>, cudaFuncAttributeMaxDynamicSharedMemorySize, SMEM);
    cudaFuncSetAttribute(gemm_tc<2,false>, cudaFuncAttributeMaxDynamicSharedMemorySize, SMEM);
    cudaFuncSetAttribute(gemm_tc<3,false>, cudaFuncAttributeMaxDynamicSharedMemorySize, SMEM);
    cudaFuncSetAttribute(gemm_tc<1,true>,  cudaFuncAttributeMaxDynamicSharedMemorySize, SMEM);

    // 0. round weights to tf32 once (fast elementwise)
    round_tf32<<<(DD*DD/4 + 255)/256, 256>>>(vw, wv, DD*DD/4);
    round_tf32<<<(DD*DD/4 + 255)/256, 256>>>(ow, wo, DD*DD/4);
    round_tf32<<<(HID*DD/4 + 255)/256, 256>>>(f1w, w1, HID*DD/4);
    round_tf32<<<(HID*DD/4 + 255)/256, 256>>>(f2w, w2, HID*DD/4);
    round_tf32<<<(FF*DD/4 + 255)/256, 256>>>(qw, wqk, FF*DD/4);
    round_tf32<<<(FF*DD/4 + 255)/256, 256>>>(kw, wqk + (size_t)FF*DD, FF*DD/4);

    // 1. x_norm = LN1(x)
    ln_kernel<<<MROWS, 256>>>(x, ln1w, ln1b, xn);
    // 2. Q,K fused: [q|k] = elu(xn @ [qw;kw]^T + [qb;kb]) + 1
    gemm_tc<1,true><<<dim3(1, MROWS/128), 256, SMEM>>>(xn, wqk, qb, kb, nullptr, q, k, MROWS, 128, DD);
    // 3. V = xn @ vw^T + vb
    gemm_tc<0,false><<<dim3(DD/128, MROWS/128), 256, SMEM>>>(xn, wv, vb, nullptr, nullptr, v, nullptr, MROWS, DD, DD);
    // 4. chunked causal linear attention
    chunk_sums<<<dim3(NCH, DD/128, BB), 256>>>(k, v, S, ks);
    prefix_S<<<(BB*FF*DD)/256, 256>>>(S);
    prefix_ks<<<BB, 64>>>(ks);
    attn_scan_chunk<<<dim3(NCH, DD/128, BB), 128>>>(q, k, v, S, ks, attn);
    // 5. y1 = x + attn @ ow^T + ob
    gemm_tc<3,false><<<dim3(DD/128, MROWS/128), 256, SMEM>>>(attn, wo, ob, nullptr, x, y1, nullptr, MROWS, DD, DD);
    // 6. h = LN2(y1)
    ln_kernel<<<MROWS, 256>>>(y1, ln2w, ln2b, h);
    // 7. hf = gelu(h @ f1w^T + f1b)
    gemm_tc<2,false><<<dim3(HID/128, MROWS/128), 256, SMEM>>>(h, w1, f1b, nullptr, nullptr, hf, nullptr, MROWS, HID, DD);
    // 8. out = y1 + hf @ f2w^T + f2b
    gemm_tc<3,false><<<dim3(DD/128, MROWS/128), 256, SMEM>>>(hf, w2, f2b, nullptr, y1, out, nullptr, MROWS, DD, HID);
}